// round 7
// baseline (speedup 1.0000x reference)
#include <cuda_runtime.h>
#include <math.h>
#include <stdint.h>

// ---------------- problem constants ----------------
#define D_MODEL  1024
#define D_STATE  16
#define D_INNER  2048
#define DT_RANK  64
#define BATCH    2
#define LENGTH   2048
#define NROW     (BATCH * LENGTH)       // 4096
#define XDBL_N   96                     // dt_rank + 2*d_state
#define NCH      16                     // scan time-chunks
#define CL       (LENGTH / NCH)         // 128 steps per chunk
#define NDN      (BATCH * D_INNER * D_STATE)   // 65536 (b,d,n) tuples
#define NSTG     7                      // GEMM pipeline stages

// ---------------- scratch (device globals; no allocation allowed) ----------------
__device__ __align__(256) float g_xz   [(size_t)NROW * (2 * D_INNER)];
__device__ __align__(256) float g_xconv[(size_t)NROW * D_INNER];
__device__ __align__(256) float g_xdbl [(size_t)NROW * XDBL_N];
__device__ __align__(256) float g_dt   [(size_t)NROW * D_INNER];
__device__ __align__(256) float g_gate [(size_t)NROW * D_INNER];   // tf32-rounded
__device__ __align__(256) float g_xr   [(size_t)NROW * D_MODEL];   // tf32-rounded x
// transposed weights, [N,K] K-major, tf32-rounded
__device__ __align__(256) float g_WtIn [(size_t)(2 * D_INNER) * D_MODEL];
__device__ __align__(256) float g_WtDt [(size_t)D_INNER * DT_RANK];
__device__ __align__(256) float g_WtOut[(size_t)D_MODEL * D_INNER];
// scan chunk transitions
__device__ __align__(256) float g_P [(size_t)NCH * NDN];
__device__ __align__(256) float g_S [(size_t)NCH * NDN];
__device__ __align__(256) float g_h0[(size_t)NCH * NDN];

// ---------------- helpers ----------------
__device__ __forceinline__ uint32_t f2tf32(float x) {
    uint32_t r;
    asm("cvt.rna.tf32.f32 %0, %1;" : "=r"(r) : "f"(x));
    return r;
}
__device__ __forceinline__ float roundtf(float x) {
    return __uint_as_float(f2tf32(x));
}
__device__ __forceinline__ uint32_t smem_u32(const void* p) {
    uint32_t a;
    asm("{ .reg .u64 t; cvta.to.shared.u64 t, %1; cvt.u32.u64 %0, t; }"
        : "=r"(a) : "l"(p));
    return a;
}
__device__ __forceinline__ void cp16(uint32_t dst, const float* src) {
    asm volatile("cp.async.cg.shared.global [%0], [%1], 16;"
                 :: "r"(dst), "l"(src) : "memory");
}
#define CP_COMMIT() asm volatile("cp.async.commit_group;" ::: "memory")
#define CP_WAIT3()  asm volatile("cp.async.wait_group 3;"  ::: "memory")

__device__ __forceinline__ void mma16n8k8(float c[4], const uint32_t a[4],
                                          const uint32_t b[2]) {
    asm volatile(
        "mma.sync.aligned.m16n8k8.row.col.f32.tf32.tf32.f32 "
        "{%0,%1,%2,%3}, {%4,%5,%6,%7}, {%8,%9}, {%0,%1,%2,%3};"
        : "+f"(c[0]), "+f"(c[1]), "+f"(c[2]), "+f"(c[3])
        : "r"(a[0]), "r"(a[1]), "r"(a[2]), "r"(a[3]), "r"(b[0]), "r"(b[1]));
}

// ---------------- tf32 mma.sync GEMM, cp.async 7-stage pipeline, 2 CTAs/SM --------
// C[M,N] = A[M,K] @ Bt[N,K]^T + bias.  Inputs pre-rounded tf32.  K mult of 32.
// CTA tile 128x128, BK=16 chunks processed in PAIRS (one barrier / 32 k).
// 256 threads = 8 warps (2m x 4n), warp tile 64x32.
// SMEM word(row,k) = row*16 + ((k>>2) ^ ((row>>1)&3))*4 + (k&3) -> conflict-free.
template <int SOFTPLUS>
__global__ __launch_bounds__(256, 2) void mma_gemm(
    const float* __restrict__ A,  int lda,
    const float* __restrict__ Bt, int ldb,
    const float* __restrict__ bias,
    float* __restrict__ C, int ldc, int K)
{
    extern __shared__ uint32_t sm[];     // As[NSTG][2048] | Bs[NSTG][2048]
    uint32_t* As = sm;
    uint32_t* Bs = sm + NSTG * 2048;
    const uint32_t sA = smem_u32(As);
    const uint32_t sB = smem_u32(Bs);

    const int tid  = threadIdx.x;
    const int lane = tid & 31;
    const int wid  = tid >> 5;
    const int wm   = wid >> 2;        // 0..1
    const int wn   = wid & 3;         // 0..3
    const int r    = lane >> 2;       // 0..7
    const int cq   = lane & 3;        // 0..3

    const int m0 = blockIdx.y * 128;
    const int n0 = blockIdx.x * 128;
    const float* Ag = A  + (size_t)m0 * lda;
    const float* Bg = Bt + (size_t)n0 * ldb;

    const int srow = tid & 127;
    const int sq0  = tid >> 7;                 // quads {sq0, sq0+2}
    const uint32_t ssw = (srow >> 1) & 3;

    float acc[4][4][4];
#pragma unroll
    for (int i = 0; i < 4; i++)
#pragma unroll
        for (int j = 0; j < 4; j++)
#pragma unroll
            for (int q = 0; q < 4; q++) acc[i][j][q] = 0.f;

    const int NC = K >> 4;            // even for all uses (4, 64, 128, 256)

    auto issue = [&](int chunk) {
        const int stage = chunk % NSTG;
        const int k0 = chunk << 4;
#pragma unroll
        for (int t = 0; t < 2; t++) {
            const int q = sq0 + t * 2;
            const uint32_t woff = (uint32_t)(stage * 2048 + srow * 16 +
                                             (((uint32_t)q ^ ssw) << 2)) << 2;
            cp16(sA + woff, Ag + (size_t)srow * lda + k0 + q * 4);
            cp16(sB + woff, Bg + (size_t)srow * ldb + k0 + q * 4);
        }
    };

    auto compute = [&](int chunk) {
        const uint32_t* A_s = As + (chunk % NSTG) * 2048;
        const uint32_t* B_s = Bs + (chunk % NSTG) * 2048;
#pragma unroll
        for (int ks = 0; ks < 2; ks++) {
            uint32_t a[4][4], b[4][2];
#pragma unroll
            for (int mi = 0; mi < 4; mi++) {
                const int rb  = wm * 64 + mi * 16 + r;
                const uint32_t swa = (rb >> 1) & 3;
                const int q0 = (2 * ks) ^ swa, q1 = (2 * ks + 1) ^ swa;
                const int b0 = rb * 16 + cq, b8 = (rb + 8) * 16 + cq;
                a[mi][0] = A_s[b0 + (q0 << 2)];
                a[mi][1] = A_s[b8 + (q0 << 2)];
                a[mi][2] = A_s[b0 + (q1 << 2)];
                a[mi][3] = A_s[b8 + (q1 << 2)];
            }
#pragma unroll
            for (int ni = 0; ni < 4; ni++) {
                const int nb = wn * 32 + ni * 8 + r;
                const uint32_t swb = (nb >> 1) & 3;
                const int base = nb * 16 + cq;
                b[ni][0] = B_s[base + ((((2 * ks)     ^ swb)) << 2)];
                b[ni][1] = B_s[base + ((((2 * ks + 1) ^ swb)) << 2)];
            }
#pragma unroll
            for (int mi = 0; mi < 4; mi++)
#pragma unroll
                for (int ni = 0; ni < 4; ni++)
                    mma16n8k8(acc[mi][ni], a[mi], b[ni]);
        }
    };

    // prologue: chunks 0..4 in flight (5 commits, possibly empty)
#pragma unroll
    for (int s = 0; s < 5; s++) {
        if (s < NC) issue(s);
        CP_COMMIT();
    }

    // pair loop: one barrier + one wait per 2 chunks
    for (int c = 0; c < NC; c += 2) {
        CP_WAIT3();                 // chunks <= c+1 have arrived
        __syncthreads();            // all warps done reading chunks <= c-1

        compute(c);
        compute(c + 1);

        // stages (c+5)%7=(c-2)%7 and (c+6)%7=(c-1)%7: read before the barrier above
        if (c + 5 < NC) issue(c + 5);
        CP_COMMIT();
        if (c + 6 < NC) issue(c + 6);
        CP_COMMIT();
    }

    // ---- epilogue ----
#pragma unroll
    for (int ni = 0; ni < 4; ni++) {
        const int col = n0 + wn * 32 + ni * 8 + cq * 2;
        const float bv0 = bias[col], bv1 = bias[col + 1];
#pragma unroll
        for (int mi = 0; mi < 4; mi++) {
            const int row0 = m0 + wm * 64 + mi * 16 + r;
            float2 o0, o1;
            o0.x = acc[mi][ni][0] + bv0;  o0.y = acc[mi][ni][1] + bv1;
            o1.x = acc[mi][ni][2] + bv0;  o1.y = acc[mi][ni][3] + bv1;
            if (SOFTPLUS) {
                o0.x = fmaxf(o0.x, 0.f) + log1pf(expf(-fabsf(o0.x)));
                o0.y = fmaxf(o0.y, 0.f) + log1pf(expf(-fabsf(o0.y)));
                o1.x = fmaxf(o1.x, 0.f) + log1pf(expf(-fabsf(o1.x)));
                o1.y = fmaxf(o1.y, 0.f) + log1pf(expf(-fabsf(o1.y)));
            }
            *(float2*)(C + (size_t)row0 * ldc + col)       = o0;
            *(float2*)(C + (size_t)(row0 + 8) * ldc + col) = o1;
        }
    }
}

// ---------------- weight transpose (+ tf32 round): D[C][R] = rnd(S[R][C]) ----------
__global__ __launch_bounds__(256) void transpose_round_kernel(
    const float* __restrict__ S, float* __restrict__ D, int R, int C)
{
    __shared__ float t[32][33];
    const int c0 = blockIdx.x * 32, r0 = blockIdx.y * 32;
    const int x = threadIdx.x, y = threadIdx.y;   // 32 x 8
#pragma unroll
    for (int i = 0; i < 32; i += 8)
        t[y + i][x] = S[(size_t)(r0 + y + i) * C + c0 + x];
    __syncthreads();
#pragma unroll
    for (int i = 0; i < 32; i += 8)
        D[(size_t)(c0 + y + i) * R + r0 + x] = roundtf(t[x][y + i]);
}

// ---------------- elementwise tf32 round (float4) ----------------
__global__ void round_tf32_kernel(const float* __restrict__ S,
                                  float* __restrict__ D, int n4)
{
    const int i = blockIdx.x * blockDim.x + threadIdx.x;
    if (i >= n4) return;
    float4 v = ((const float4*)S)[i];
    v.x = roundtf(v.x); v.y = roundtf(v.y);
    v.z = roundtf(v.z); v.w = roundtf(v.w);
    ((float4*)D)[i] = v;
}

// ---------------- skinny GEMM: x_dbl[M,96] = A[M,K] @ B[K,96] + bias ----------------
// 768 threads: r = tid/24 (32 rows), c0 = (tid%24)*4 (4 cols per thread).
__global__ __launch_bounds__(768) void gemm_n96(
    const float* __restrict__ A,
    const float* __restrict__ B,
    const float* __restrict__ bias,
    float* __restrict__ C,
    int M, int K)
{
    __shared__ float As[32][33];
    __shared__ float Bs[32][96];
    const int tid = threadIdx.x;
    const int m0 = blockIdx.x * 32;
    const int r  = tid / 24;
    const int c0 = (tid % 24) * 4;

    float acc[4] = {0.f, 0.f, 0.f, 0.f};

    for (int k0 = 0; k0 < K; k0 += 32) {
        __syncthreads();
        if (tid < 256) {   // A: 32x32 floats = 256 float4
            int arow = tid >> 3, akk = (tid & 7) * 4;
            float4 v = *(const float4*)&A[(size_t)(m0 + arow) * K + k0 + akk];
            As[arow][akk + 0] = v.x; As[arow][akk + 1] = v.y;
            As[arow][akk + 2] = v.z; As[arow][akk + 3] = v.w;
        }
        {   // B: 32x96 floats = 768 float4, one per thread
            int brw = tid / 24, bcc = (tid % 24) * 4;
            float4 v = *(const float4*)&B[(size_t)(k0 + brw) * XDBL_N + bcc];
            *(float4*)&Bs[brw][bcc] = v;
        }
        __syncthreads();
#pragma unroll
        for (int kk = 0; kk < 32; kk++) {
            const float a = As[r][kk];
            const float4 b4 = *(const float4*)&Bs[kk][c0];
            acc[0] = fmaf(a, b4.x, acc[0]);
            acc[1] = fmaf(a, b4.y, acc[1]);
            acc[2] = fmaf(a, b4.z, acc[2]);
            acc[3] = fmaf(a, b4.w, acc[3]);
        }
    }
#pragma unroll
    for (int i = 0; i < 4; i++) {
        float v = acc[i] + bias[c0 + i];
        if (c0 < DT_RANK) v = roundtf(v);
        C[(size_t)(m0 + r) * XDBL_N + c0 + i] = v;
    }
}

// ---------------- depthwise causal mean-3 conv + SiLU ----------------
__global__ void conv_silu_kernel()
{
    const int i = blockIdx.x * blockDim.x + threadIdx.x;
    if (i >= NROW * D_INNER) return;
    const int d   = i & (D_INNER - 1);
    const int row = i >> 11;
    const int t   = row & (LENGTH - 1);
    const float* p = g_xz + (size_t)row * (2 * D_INNER) + d;
    float v = p[0];
    if (t >= 1) v += p[-(2 * D_INNER)];
    if (t >= 2) v += p[-2 * (2 * D_INNER)];
    v *= (1.0f / 3.0f);
    g_xconv[i] = v / (1.f + __expf(-v));
}

// ======================= 3-phase chunked selective scan =======================
__global__ __launch_bounds__(256) void scan_p1(const float* __restrict__ A_log)
{
    const int TT = 32;
    __shared__ float s_dt[TT][16], s_x[TT][16], s_B[TT][16];

    const int tid   = threadIdx.x;
    const int chunk = blockIdx.x & (NCH - 1);
    const int dblk  = (blockIdx.x >> 4) & 127;
    const int b     = blockIdx.x >> 11;
    const int d0    = dblk << 4;
    const int lane  = tid & 31, w = tid >> 5;
    const int half  = lane >> 4, n = lane & 15;
    const int ch    = (w << 1) | half;
    const int d     = d0 + ch;

    const float a = -__expf(A_log[d * D_STATE + n]);
    float h = 0.f, P = 1.f;
    const size_t rowbase = (size_t)b * LENGTH + (size_t)chunk * CL;

    for (int t0 = 0; t0 < CL; t0 += TT) {
        __syncthreads();
        for (int e = tid; e < TT * 16; e += 256) {
            const int tt = e >> 4, cc = e & 15;
            const size_t row = rowbase + t0 + tt;
            s_dt[tt][cc] = g_dt   [row * D_INNER + d0 + cc];
            s_x [tt][cc] = g_xconv[row * D_INNER + d0 + cc];
            s_B [tt][cc] = g_xdbl [row * XDBL_N + DT_RANK + cc];
        }
        __syncthreads();
#pragma unroll 8
        for (int tt = 0; tt < TT; tt++) {
            const float dtv = s_dt[tt][ch];
            const float dA  = __expf(a * dtv);
            P *= dA;
            h = fmaf(dA, h, dtv * s_x[tt][ch] * s_B[tt][n]);
        }
    }
    const size_t idx = ((size_t)b * D_INNER + d) * D_STATE + n;
    g_P[(size_t)chunk * NDN + idx] = P;
    g_S[(size_t)chunk * NDN + idx] = h;
}

__global__ __launch_bounds__(256) void scan_p2()
{
    const int i = blockIdx.x * blockDim.x + threadIdx.x;   // 0..NDN-1
    if (i >= NDN) return;
    float h = 0.f;
#pragma unroll
    for (int c = 0; c < NCH; c++) {
        g_h0[(size_t)c * NDN + i] = h;
        h = fmaf(g_P[(size_t)c * NDN + i], h, g_S[(size_t)c * NDN + i]);
    }
}

__global__ __launch_bounds__(256) void scan_p3(const float* __restrict__ A_log,
                                               const float* __restrict__ Dv)
{
    const int TT = 32;
    __shared__ float s_dt[TT][16], s_x[TT][16], s_B[TT][16], s_C[TT][16];

    const int tid   = threadIdx.x;
    const int chunk = blockIdx.x & (NCH - 1);
    const int dblk  = (blockIdx.x >> 4) & 127;
    const int b     = blockIdx.x >> 11;
    const int d0    = dblk << 4;
    const int lane  = tid & 31, w = tid >> 5;
    const int half  = lane >> 4, n = lane & 15;
    const int ch    = (w << 1) | half;
    const int d     = d0 + ch;

    const float a  = -__expf(A_log[d * D_STATE + n]);
    const float Dd = Dv[d];
    const size_t idx = ((size_t)b * D_INNER + d) * D_STATE + n;
    float h = g_h0[(size_t)chunk * NDN + idx];
    const size_t rowbase = (size_t)b * LENGTH + (size_t)chunk * CL;

    for (int t0 = 0; t0 < CL; t0 += TT) {
        __syncthreads();
        for (int e = tid; e < TT * 16; e += 256) {
            const int tt = e >> 4, cc = e & 15;
            const size_t row = rowbase + t0 + tt;
            s_dt[tt][cc] = g_dt   [row * D_INNER + d0 + cc];
            s_x [tt][cc] = g_xconv[row * D_INNER + d0 + cc];
            s_B [tt][cc] = g_xdbl [row * XDBL_N + DT_RANK + cc];
            s_C [tt][cc] = g_xdbl [row * XDBL_N + DT_RANK + D_STATE + cc];
        }
        __syncthreads();
#pragma unroll 4
        for (int tt = 0; tt < TT; tt++) {
            const float dtv = s_dt[tt][ch];
            const float xv  = s_x [tt][ch];
            const float dA  = __expf(a * dtv);
            h = fmaf(dA, h, dtv * xv * s_B[tt][n]);
            float yc = h * s_C[tt][n];
            yc += __shfl_xor_sync(0xffffffffu, yc, 8);
            yc += __shfl_xor_sync(0xffffffffu, yc, 4);
            yc += __shfl_xor_sync(0xffffffffu, yc, 2);
            yc += __shfl_xor_sync(0xffffffffu, yc, 1);
            if (n == 0) {
                const size_t row = rowbase + t0 + tt;
                const float zv = g_xz[row * (2 * D_INNER) + D_INNER + d];
                const float sz = zv / (1.f + __expf(-zv));
                const float y  = fmaf(xv, Dd, yc);
                g_gate[row * D_INNER + d] = roundtf(y * sz);
            }
        }
    }
}

// ---------------- host launcher ----------------
extern "C" void kernel_launch(void* const* d_in, const int* in_sizes, int n_in,
                              void* d_out, int out_size)
{
    (void)in_sizes; (void)n_in; (void)out_size;
    const float* x     = (const float*)d_in[0];
    const float* W_in  = (const float*)d_in[1];
    const float* b_in  = (const float*)d_in[2];
    const float* W_x   = (const float*)d_in[3];
    const float* b_x   = (const float*)d_in[4];
    const float* W_dt  = (const float*)d_in[5];
    const float* b_dt  = (const float*)d_in[6];
    const float* A_log = (const float*)d_in[7];
    const float* Dp    = (const float*)d_in[8];
    const float* W_out = (const float*)d_in[9];
    const float* b_out = (const float*)d_in[10];
    float* out = (float*)d_out;

    float *xz, *xconv, *xdbl, *dt, *gate, *xr, *WtIn, *WtDt, *WtOut;
    cudaGetSymbolAddress((void**)&xz,    g_xz);
    cudaGetSymbolAddress((void**)&xconv, g_xconv);
    cudaGetSymbolAddress((void**)&xdbl,  g_xdbl);
    cudaGetSymbolAddress((void**)&dt,    g_dt);
    cudaGetSymbolAddress((void**)&gate,  g_gate);
    cudaGetSymbolAddress((void**)&xr,    g_xr);
    cudaGetSymbolAddress((void**)&WtIn,  g_WtIn);
    cudaGetSymbolAddress((void**)&WtDt,  g_WtDt);
    cudaGetSymbolAddress((void**)&WtOut, g_WtOut);

    const int DSMEM = NSTG * 2048 * 2 * 4;   // 112KB (2 CTAs/SM on 228KB)
    cudaFuncSetAttribute(mma_gemm<0>, cudaFuncAttributeMaxDynamicSharedMemorySize, DSMEM);
    cudaFuncSetAttribute(mma_gemm<1>, cudaFuncAttributeMaxDynamicSharedMemorySize, DSMEM);

    // 0-2) pre-round x, transpose W_in / W_dt
    round_tf32_kernel<<<(NROW * D_MODEL / 4 + 255) / 256, 256>>>(x, xr, NROW * D_MODEL / 4);
    transpose_round_kernel<<<dim3(4096 / 32, 1024 / 32), dim3(32, 8)>>>(W_in, WtIn, 1024, 4096);
    transpose_round_kernel<<<dim3(2048 / 32,   64 / 32), dim3(32, 8)>>>(W_dt, WtDt,   64, 2048);

    // 3) xz = x @ W_in + b_in      [4096,1024] x [1024,4096]   <- profiled slot
    mma_gemm<0><<<dim3(4096 / 128, NROW / 128), 256, DSMEM>>>(
        xr, D_MODEL, WtIn, D_MODEL, b_in, xz, 2 * D_INNER, D_MODEL);

    // 4) causal mean-3 conv + SiLU
    conv_silu_kernel<<<(NROW * D_INNER) / 256, 256>>>();

    // 5) x_dbl = x_conv @ W_x + b_x   [4096,2048] x [2048,96]
    gemm_n96<<<NROW / 32, 768>>>(xconv, W_x, b_x, xdbl, NROW, D_INNER);

    // 6) dt = softplus(x_dbl[:, :64] @ W_dt + b_dt)  [4096,64] x [64,2048]
    mma_gemm<1><<<dim3(D_INNER / 128, NROW / 128), 256, DSMEM>>>(
        xdbl, XDBL_N, WtDt, DT_RANK, b_dt, dt, D_INNER, DT_RANK);

    // 7-9) chunked selective scan
    scan_p1<<<BATCH * 128 * NCH, 256>>>(A_log);
    scan_p2<<<NDN / 256, 256>>>();
    scan_p3<<<BATCH * 128 * NCH, 256>>>(A_log, Dp);

    // 10) transpose W_out
    transpose_round_kernel<<<dim3(1024 / 32, 2048 / 32), dim3(32, 8)>>>(W_out, WtOut, 2048, 1024);

    // 11) out = gate @ W_out + b_out   [4096,2048] x [2048,1024]
    mma_gemm<0><<<dim3(D_MODEL / 128, NROW / 128), 256, DSMEM>>>(
        gate, D_INNER, WtOut, D_INNER, b_out, out, D_MODEL, D_INNER);
}

// round 8
// speedup vs baseline: 1.0323x; 1.0323x over previous
#include <cuda_runtime.h>
#include <math.h>
#include <stdint.h>

// ---------------- problem constants ----------------
#define D_MODEL  1024
#define D_STATE  16
#define D_INNER  2048
#define DT_RANK  64
#define BATCH    2
#define LENGTH   2048
#define NROW     (BATCH * LENGTH)       // 4096
#define XDBL_N   96                     // dt_rank + 2*d_state
#define NCH      16                     // scan time-chunks
#define CL       (LENGTH / NCH)         // 128 steps per chunk
#define NDN      (BATCH * D_INNER * D_STATE)   // 65536 (b,d,n) tuples
#define NSTG     5                      // GEMM pipeline stages

// k-permutation within 16-element groups: p = (k&3)*4 + (k>>2)
// inverse: k = (p&3)*4 + (p>>2)

// ---------------- scratch (device globals; no allocation allowed) ----------------
__device__ __align__(256) float g_xz   [(size_t)NROW * (2 * D_INNER)];
__device__ __align__(256) float g_xconv[(size_t)NROW * D_INNER];
__device__ __align__(256) float g_xdbl [(size_t)NROW * XDBL_N];   // cols<64 k-permuted
__device__ __align__(256) float g_dt   [(size_t)NROW * D_INNER];
__device__ __align__(256) float g_gate [(size_t)NROW * D_INNER];  // tf32 + k-permuted
__device__ __align__(256) float g_xr   [(size_t)NROW * D_MODEL];  // tf32 + k-permuted
// transposed weights, [N,K] K-major, tf32-rounded + k-permuted
__device__ __align__(256) float g_WtIn [(size_t)(2 * D_INNER) * D_MODEL];
__device__ __align__(256) float g_WtDt [(size_t)D_INNER * DT_RANK];
__device__ __align__(256) float g_WtOut[(size_t)D_MODEL * D_INNER];
// scan chunk transitions
__device__ __align__(256) float g_P [(size_t)NCH * NDN];
__device__ __align__(256) float g_S [(size_t)NCH * NDN];
__device__ __align__(256) float g_h0[(size_t)NCH * NDN];

// ---------------- helpers ----------------
__device__ __forceinline__ uint32_t f2tf32(float x) {
    uint32_t r;
    asm("cvt.rna.tf32.f32 %0, %1;" : "=r"(r) : "f"(x));
    return r;
}
__device__ __forceinline__ float roundtf(float x) {
    return __uint_as_float(f2tf32(x));
}
__device__ __forceinline__ uint32_t smem_u32(const void* p) {
    uint32_t a;
    asm("{ .reg .u64 t; cvta.to.shared.u64 t, %1; cvt.u32.u64 %0, t; }"
        : "=r"(a) : "l"(p));
    return a;
}
__device__ __forceinline__ void cp16(uint32_t dst, const float* src) {
    asm volatile("cp.async.cg.shared.global [%0], [%1], 16;"
                 :: "r"(dst), "l"(src) : "memory");
}
#define CP_COMMIT() asm volatile("cp.async.commit_group;" ::: "memory")
#define CP_WAIT3()  asm volatile("cp.async.wait_group 3;"  ::: "memory")

__device__ __forceinline__ void mma16n8k8(float c[4], uint32_t a0, uint32_t a1,
                                          uint32_t a2, uint32_t a3,
                                          uint32_t b0, uint32_t b1) {
    asm volatile(
        "mma.sync.aligned.m16n8k8.row.col.f32.tf32.tf32.f32 "
        "{%0,%1,%2,%3}, {%4,%5,%6,%7}, {%8,%9}, {%0,%1,%2,%3};"
        : "+f"(c[0]), "+f"(c[1]), "+f"(c[2]), "+f"(c[3])
        : "r"(a0), "r"(a1), "r"(a2), "r"(a3), "r"(b0), "r"(b1));
}
#define FU(x) __float_as_uint(x)

// ---------------- tf32 mma.sync GEMM, LDS.128 fragments, 2 CTAs/SM ----------------
// C[M,N] = A[M,K] @ Bt[N,K]^T + bias.  A/Bt pre-rounded tf32 AND k-permuted
// within 16-element k-groups (p = (k&3)*4 + (k>>2)).
// SMEM per stage: plain [row][16] floats (no swizzle needed): thread (r,cq)'s
// fragment words for BOTH k-steps of a chunk = one contiguous float4.
// CTA tile 128x128, BK=16, 256 threads = 8 warps (2m x 4n), warp tile 64x32.
template <int SOFTPLUS>
__global__ __launch_bounds__(256, 2) void mma_gemm(
    const float* __restrict__ A,  int lda,
    const float* __restrict__ Bt, int ldb,
    const float* __restrict__ bias,
    float* __restrict__ C, int ldc, int K)
{
    extern __shared__ float sm[];     // As[NSTG][2048] | Bs[NSTG][2048]
    float* As = sm;
    float* Bs = sm + NSTG * 2048;
    const uint32_t sA = smem_u32(As);
    const uint32_t sB = smem_u32(Bs);

    const int tid  = threadIdx.x;
    const int lane = tid & 31;
    const int wid  = tid >> 5;
    const int wm   = wid >> 2;        // 0..1
    const int wn   = wid & 3;         // 0..3
    const int r    = lane >> 2;       // 0..7
    const int cq   = lane & 3;        // 0..3

    const int m0 = blockIdx.y * 128;
    const int n0 = blockIdx.x * 128;
    const float* Ag = A  + (size_t)m0 * lda;
    const float* Bg = Bt + (size_t)n0 * ldb;

    const int srow = tid & 127;
    const int sq0  = tid >> 7;                 // quads {sq0, sq0+2}

    float acc[4][4][4];
#pragma unroll
    for (int i = 0; i < 4; i++)
#pragma unroll
        for (int j = 0; j < 4; j++)
#pragma unroll
            for (int q = 0; q < 4; q++) acc[i][j][q] = 0.f;

    const int NC = K >> 4;

    auto issue = [&](int chunk) {
        const int stage = chunk % NSTG;
        const int k0 = chunk << 4;
#pragma unroll
        for (int t = 0; t < 2; t++) {
            const int q = sq0 + t * 2;
            const uint32_t woff = (uint32_t)(stage * 2048 + srow * 16 + q * 4) << 2;
            cp16(sA + woff, Ag + (size_t)srow * lda + k0 + q * 4);
            cp16(sB + woff, Bg + (size_t)srow * ldb + k0 + q * 4);
        }
    };

    // prologue: 4 chunks in flight
#pragma unroll
    for (int s = 0; s < NSTG - 1; s++) {
        if (s < NC) issue(s);
        CP_COMMIT();
    }

    for (int c = 0; c < NC; c++) {
        CP_WAIT3();
        __syncthreads();

        const float4* A4 = (const float4*)(As + (c % NSTG) * 2048);
        const float4* B4 = (const float4*)(Bs + (c % NSTG) * 2048);

        float4 bf[4];
#pragma unroll
        for (int ni = 0; ni < 4; ni++)
            bf[ni] = B4[(wn * 32 + ni * 8 + r) * 4 + cq];

#pragma unroll
        for (int mi = 0; mi < 4; mi++) {
            const int rb = wm * 64 + mi * 16 + r;
            const float4 a0v = A4[rb * 4 + cq];          // row rb:   k = cq,cq+4,cq+8,cq+12
            const float4 a1v = A4[(rb + 8) * 4 + cq];    // row rb+8: same k's
#pragma unroll
            for (int ni = 0; ni < 4; ni++) {
                // k-step 0 (k = 0..7)
                mma16n8k8(acc[mi][ni], FU(a0v.x), FU(a1v.x), FU(a0v.y), FU(a1v.y),
                          FU(bf[ni].x), FU(bf[ni].y));
                // k-step 1 (k = 8..15)
                mma16n8k8(acc[mi][ni], FU(a0v.z), FU(a1v.z), FU(a0v.w), FU(a1v.w),
                          FU(bf[ni].z), FU(bf[ni].w));
            }
        }

        if (c + NSTG - 1 < NC) issue(c + NSTG - 1);
        CP_COMMIT();
    }

    // ---- epilogue ----
#pragma unroll
    for (int ni = 0; ni < 4; ni++) {
        const int col = n0 + wn * 32 + ni * 8 + cq * 2;
        const float bv0 = bias[col], bv1 = bias[col + 1];
#pragma unroll
        for (int mi = 0; mi < 4; mi++) {
            const int row0 = m0 + wm * 64 + mi * 16 + r;
            float2 o0, o1;
            o0.x = acc[mi][ni][0] + bv0;  o0.y = acc[mi][ni][1] + bv1;
            o1.x = acc[mi][ni][2] + bv0;  o1.y = acc[mi][ni][3] + bv1;
            if (SOFTPLUS) {
                o0.x = fmaxf(o0.x, 0.f) + log1pf(expf(-fabsf(o0.x)));
                o0.y = fmaxf(o0.y, 0.f) + log1pf(expf(-fabsf(o0.y)));
                o1.x = fmaxf(o1.x, 0.f) + log1pf(expf(-fabsf(o1.x)));
                o1.y = fmaxf(o1.y, 0.f) + log1pf(expf(-fabsf(o1.y)));
            }
            *(float2*)(C + (size_t)row0 * ldc + col)       = o0;
            *(float2*)(C + (size_t)(row0 + 8) * ldc + col) = o1;
        }
    }
}

// -------- weight transpose + tf32 round + k-permute: D[C][R(K-perm)] --------
__global__ __launch_bounds__(256) void transpose_round_kernel(
    const float* __restrict__ S, float* __restrict__ D, int R, int C)
{
    __shared__ float t[32][33];
    const int c0 = blockIdx.x * 32, r0 = blockIdx.y * 32;
    const int x = threadIdx.x, y = threadIdx.y;   // 32 x 8
#pragma unroll
    for (int i = 0; i < 32; i += 8)
        t[y + i][x] = S[(size_t)(r0 + y + i) * C + c0 + x];
    __syncthreads();
    // permuted column within 16-group: (x&16) + (x&3)*4 + ((x&15)>>2)
    const int xx = (x & 16) + ((x & 3) << 2) + ((x & 15) >> 2);
#pragma unroll
    for (int i = 0; i < 32; i += 8)
        D[(size_t)(c0 + y + i) * R + r0 + xx] = roundtf(t[x][y + i]);
}

// -------- elementwise tf32 round + k-permute (gather 4 stride-4, store float4) ------
__global__ void round_perm_kernel(const float* __restrict__ S,
                                  float* __restrict__ D, int n4, int ldq)
{
    const int i = blockIdx.x * blockDim.x + threadIdx.x;
    if (i >= n4) return;
    const int f = i % ldq;                 // float4 index within row
    const int rowbase = (i - f) * 4;       // row start (floats)
    const int g = f >> 2, cq = f & 3;      // 16-group, output quad
    const float* src = S + rowbase + g * 16 + cq;
    float4 o;
    o.x = roundtf(src[0]);
    o.y = roundtf(src[4]);
    o.z = roundtf(src[8]);
    o.w = roundtf(src[12]);
    ((float4*)D)[i] = o;
}

// ---------------- skinny GEMM: x_dbl[M,96] = A[M,K] @ B[K,96] + bias ----------------
// 768 threads. cols < 64 (dt-lowrank) stored tf32-rounded + k-permuted.
__global__ __launch_bounds__(768) void gemm_n96(
    const float* __restrict__ A,
    const float* __restrict__ B,
    const float* __restrict__ bias,
    float* __restrict__ C,
    int M, int K)
{
    __shared__ float As[32][33];
    __shared__ float Bs[32][96];
    const int tid = threadIdx.x;
    const int m0 = blockIdx.x * 32;
    const int r  = tid / 24;
    const int c0 = (tid % 24) * 4;

    float acc[4] = {0.f, 0.f, 0.f, 0.f};

    for (int k0 = 0; k0 < K; k0 += 32) {
        __syncthreads();
        if (tid < 256) {   // A: 32x32 floats = 256 float4
            int arow = tid >> 3, akk = (tid & 7) * 4;
            float4 v = *(const float4*)&A[(size_t)(m0 + arow) * K + k0 + akk];
            As[arow][akk + 0] = v.x; As[arow][akk + 1] = v.y;
            As[arow][akk + 2] = v.z; As[arow][akk + 3] = v.w;
        }
        {   // B: 32x96 floats = 768 float4, one per thread
            int brw = tid / 24, bcc = (tid % 24) * 4;
            float4 v = *(const float4*)&B[(size_t)(k0 + brw) * XDBL_N + bcc];
            *(float4*)&Bs[brw][bcc] = v;
        }
        __syncthreads();
#pragma unroll
        for (int kk = 0; kk < 32; kk++) {
            const float a = As[r][kk];
            const float4 b4 = *(const float4*)&Bs[kk][c0];
            acc[0] = fmaf(a, b4.x, acc[0]);
            acc[1] = fmaf(a, b4.y, acc[1]);
            acc[2] = fmaf(a, b4.z, acc[2]);
            acc[3] = fmaf(a, b4.w, acc[3]);
        }
    }
    if (c0 < DT_RANK) {
        // k-permuted scatter: col = (c0&~15) + i*4 + (c0&15)/4
        const int gbase = (c0 & ~15), q = (c0 & 15) >> 2;
#pragma unroll
        for (int i = 0; i < 4; i++)
            C[(size_t)(m0 + r) * XDBL_N + gbase + i * 4 + q] =
                roundtf(acc[i] + bias[c0 + i]);
    } else {
#pragma unroll
        for (int i = 0; i < 4; i++)
            C[(size_t)(m0 + r) * XDBL_N + c0 + i] = acc[i] + bias[c0 + i];
    }
}

// ---------------- depthwise causal mean-3 conv + SiLU ----------------
__global__ void conv_silu_kernel()
{
    const int i = blockIdx.x * blockDim.x + threadIdx.x;
    if (i >= NROW * D_INNER) return;
    const int d   = i & (D_INNER - 1);
    const int row = i >> 11;
    const int t   = row & (LENGTH - 1);
    const float* p = g_xz + (size_t)row * (2 * D_INNER) + d;
    float v = p[0];
    if (t >= 1) v += p[-(2 * D_INNER)];
    if (t >= 2) v += p[-2 * (2 * D_INNER)];
    v *= (1.0f / 3.0f);
    g_xconv[i] = v / (1.f + __expf(-v));
}

// ======================= 3-phase chunked selective scan =======================
__global__ __launch_bounds__(256) void scan_p1(const float* __restrict__ A_log)
{
    const int TT = 32;
    __shared__ float s_dt[TT][16], s_x[TT][16], s_B[TT][16];

    const int tid   = threadIdx.x;
    const int chunk = blockIdx.x & (NCH - 1);
    const int dblk  = (blockIdx.x >> 4) & 127;
    const int b     = blockIdx.x >> 11;
    const int d0    = dblk << 4;
    const int lane  = tid & 31, w = tid >> 5;
    const int half  = lane >> 4, n = lane & 15;
    const int ch    = (w << 1) | half;
    const int d     = d0 + ch;

    const float a = -__expf(A_log[d * D_STATE + n]);
    float h = 0.f, P = 1.f;
    const size_t rowbase = (size_t)b * LENGTH + (size_t)chunk * CL;

    for (int t0 = 0; t0 < CL; t0 += TT) {
        __syncthreads();
        for (int e = tid; e < TT * 16; e += 256) {
            const int tt = e >> 4, cc = e & 15;
            const size_t row = rowbase + t0 + tt;
            s_dt[tt][cc] = g_dt   [row * D_INNER + d0 + cc];
            s_x [tt][cc] = g_xconv[row * D_INNER + d0 + cc];
            s_B [tt][cc] = g_xdbl [row * XDBL_N + DT_RANK + cc];
        }
        __syncthreads();
#pragma unroll 8
        for (int tt = 0; tt < TT; tt++) {
            const float dtv = s_dt[tt][ch];
            const float dA  = __expf(a * dtv);
            P *= dA;
            h = fmaf(dA, h, dtv * s_x[tt][ch] * s_B[tt][n]);
        }
    }
    const size_t idx = ((size_t)b * D_INNER + d) * D_STATE + n;
    g_P[(size_t)chunk * NDN + idx] = P;
    g_S[(size_t)chunk * NDN + idx] = h;
}

__global__ __launch_bounds__(256) void scan_p2()
{
    const int i = blockIdx.x * blockDim.x + threadIdx.x;   // 0..NDN-1
    if (i >= NDN) return;
    float h = 0.f;
#pragma unroll
    for (int c = 0; c < NCH; c++) {
        g_h0[(size_t)c * NDN + i] = h;
        h = fmaf(g_P[(size_t)c * NDN + i], h, g_S[(size_t)c * NDN + i]);
    }
}

__global__ __launch_bounds__(256) void scan_p3(const float* __restrict__ A_log,
                                               const float* __restrict__ Dv)
{
    const int TT = 32;
    __shared__ float s_dt[TT][16], s_x[TT][16], s_B[TT][16], s_C[TT][16];

    const int tid   = threadIdx.x;
    const int chunk = blockIdx.x & (NCH - 1);
    const int dblk  = (blockIdx.x >> 4) & 127;
    const int b     = blockIdx.x >> 11;
    const int d0    = dblk << 4;
    const int lane  = tid & 31, w = tid >> 5;
    const int half  = lane >> 4, n = lane & 15;
    const int ch    = (w << 1) | half;
    const int d     = d0 + ch;

    const float a  = -__expf(A_log[d * D_STATE + n]);
    const float Dd = Dv[d];
    const size_t idx = ((size_t)b * D_INNER + d) * D_STATE + n;
    float h = g_h0[(size_t)chunk * NDN + idx];
    const size_t rowbase = (size_t)b * LENGTH + (size_t)chunk * CL;

    // k-permuted output channel (within the 16-wide block)
    const int dperm = d0 + ((ch & 3) << 2) + (ch >> 2);

    for (int t0 = 0; t0 < CL; t0 += TT) {
        __syncthreads();
        for (int e = tid; e < TT * 16; e += 256) {
            const int tt = e >> 4, cc = e & 15;
            const size_t row = rowbase + t0 + tt;
            s_dt[tt][cc] = g_dt   [row * D_INNER + d0 + cc];
            s_x [tt][cc] = g_xconv[row * D_INNER + d0 + cc];
            s_B [tt][cc] = g_xdbl [row * XDBL_N + DT_RANK + cc];
            s_C [tt][cc] = g_xdbl [row * XDBL_N + DT_RANK + D_STATE + cc];
        }
        __syncthreads();
#pragma unroll 4
        for (int tt = 0; tt < TT; tt++) {
            const float dtv = s_dt[tt][ch];
            const float xv  = s_x [tt][ch];
            const float dA  = __expf(a * dtv);
            h = fmaf(dA, h, dtv * xv * s_B[tt][n]);
            float yc = h * s_C[tt][n];
            yc += __shfl_xor_sync(0xffffffffu, yc, 8);
            yc += __shfl_xor_sync(0xffffffffu, yc, 4);
            yc += __shfl_xor_sync(0xffffffffu, yc, 2);
            yc += __shfl_xor_sync(0xffffffffu, yc, 1);
            if (n == 0) {
                const size_t row = rowbase + t0 + tt;
                const float zv = g_xz[row * (2 * D_INNER) + D_INNER + d];
                const float sz = zv / (1.f + __expf(-zv));
                const float y  = fmaf(xv, Dd, yc);
                g_gate[row * D_INNER + dperm] = roundtf(y * sz);
            }
        }
    }
}

// ---------------- host launcher ----------------
extern "C" void kernel_launch(void* const* d_in, const int* in_sizes, int n_in,
                              void* d_out, int out_size)
{
    (void)in_sizes; (void)n_in; (void)out_size;
    const float* x     = (const float*)d_in[0];
    const float* W_in  = (const float*)d_in[1];
    const float* b_in  = (const float*)d_in[2];
    const float* W_x   = (const float*)d_in[3];
    const float* b_x   = (const float*)d_in[4];
    const float* W_dt  = (const float*)d_in[5];
    const float* b_dt  = (const float*)d_in[6];
    const float* A_log = (const float*)d_in[7];
    const float* Dp    = (const float*)d_in[8];
    const float* W_out = (const float*)d_in[9];
    const float* b_out = (const float*)d_in[10];
    float* out = (float*)d_out;

    float *xz, *xconv, *xdbl, *dt, *gate, *xr, *WtIn, *WtDt, *WtOut;
    cudaGetSymbolAddress((void**)&xz,    g_xz);
    cudaGetSymbolAddress((void**)&xconv, g_xconv);
    cudaGetSymbolAddress((void**)&xdbl,  g_xdbl);
    cudaGetSymbolAddress((void**)&dt,    g_dt);
    cudaGetSymbolAddress((void**)&gate,  g_gate);
    cudaGetSymbolAddress((void**)&xr,    g_xr);
    cudaGetSymbolAddress((void**)&WtIn,  g_WtIn);
    cudaGetSymbolAddress((void**)&WtDt,  g_WtDt);
    cudaGetSymbolAddress((void**)&WtOut, g_WtOut);

    const int DSMEM = NSTG * 2048 * 2 * 4;   // 80KB -> 2 CTAs/SM
    cudaFuncSetAttribute(mma_gemm<0>, cudaFuncAttributeMaxDynamicSharedMemorySize, DSMEM);
    cudaFuncSetAttribute(mma_gemm<1>, cudaFuncAttributeMaxDynamicSharedMemorySize, DSMEM);

    // 0-2) pre-round+permute x, transpose+permute W_in / W_dt
    round_perm_kernel<<<(NROW * D_MODEL / 4 + 255) / 256, 256>>>(
        x, xr, NROW * D_MODEL / 4, D_MODEL / 4);
    transpose_round_kernel<<<dim3(4096 / 32, 1024 / 32), dim3(32, 8)>>>(W_in, WtIn, 1024, 4096);
    transpose_round_kernel<<<dim3(2048 / 32,   64 / 32), dim3(32, 8)>>>(W_dt, WtDt,   64, 2048);

    // 3) xz = x @ W_in + b_in      [4096,1024] x [1024,4096]   <- profiled slot
    mma_gemm<0><<<dim3(4096 / 128, NROW / 128), 256, DSMEM>>>(
        xr, D_MODEL, WtIn, D_MODEL, b_in, xz, 2 * D_INNER, D_MODEL);

    // 4) causal mean-3 conv + SiLU
    conv_silu_kernel<<<(NROW * D_INNER) / 256, 256>>>();

    // 5) x_dbl = x_conv @ W_x + b_x   [4096,2048] x [2048,96]
    gemm_n96<<<NROW / 32, 768>>>(xconv, W_x, b_x, xdbl, NROW, D_INNER);

    // 6) dt = softplus(x_dbl[:, :64] @ W_dt + b_dt)  [4096,64] x [64,2048]
    mma_gemm<1><<<dim3(D_INNER / 128, NROW / 128), 256, DSMEM>>>(
        xdbl, XDBL_N, WtDt, DT_RANK, b_dt, dt, D_INNER, DT_RANK);

    // 7-9) chunked selective scan
    scan_p1<<<BATCH * 128 * NCH, 256>>>(A_log);
    scan_p2<<<NDN / 256, 256>>>();
    scan_p3<<<BATCH * 128 * NCH, 256>>>(A_log, Dp);

    // 10) transpose+permute W_out
    transpose_round_kernel<<<dim3(1024 / 32, 2048 / 32), dim3(32, 8)>>>(W_out, WtOut, 2048, 1024);

    // 11) out = gate @ W_out + b_out   [4096,2048] x [2048,1024]
    mma_gemm<0><<<dim3(D_MODEL / 128, NROW / 128), 256, DSMEM>>>(
        gate, D_INNER, WtOut, D_INNER, b_out, out, D_MODEL, D_INNER);
}

// round 9
// speedup vs baseline: 1.3016x; 1.2608x over previous
#include <cuda_runtime.h>
#include <cuda_fp16.h>
#include <math.h>
#include <stdint.h>

// ---------------- problem constants ----------------
#define D_MODEL  1024
#define D_STATE  16
#define D_INNER  2048
#define DT_RANK  64
#define BATCH    2
#define LENGTH   2048
#define NROW     (BATCH * LENGTH)       // 4096
#define XDBL_N   96
#define NCH      16                     // scan time-chunks
#define CL       (LENGTH / NCH)         // 128 steps per chunk
#define NDN      (BATCH * D_INNER * D_STATE)   // 65536
#define NSTG     5                      // GEMM pipeline stages (BK=32)

// k-permutation within 32-element groups (fp16 m16n8k16 fragment gather):
// p(k) = ((k>>1)&3)*8 + (k&1) + ((k>>3)&1)*2 + ((k>>4)&1)*4
__host__ __device__ __forceinline__ int kperm32(int k) {
    return (((k >> 1) & 3) << 3) + (k & 1) + (((k >> 3) & 1) << 1) + (((k >> 4) & 1) << 2);
}

// ---------------- scratch (device globals; no allocation allowed) ----------------
__device__ __align__(256) float  g_xz   [(size_t)NROW * (2 * D_INNER)];
__device__ __align__(256) float  g_xconv[(size_t)NROW * D_INNER];
__device__ __align__(256) __half g_dtlr [(size_t)NROW * DT_RANK];   // k-permuted fp16
__device__ __align__(256) float  g_BC   [(size_t)NROW * 32];        // B|C for scan
__device__ __align__(256) float  g_dt   [(size_t)NROW * D_INNER];
__device__ __align__(256) __half g_gate [(size_t)NROW * D_INNER];   // fp16 + k-permuted
__device__ __align__(256) __half g_xr   [(size_t)NROW * D_MODEL];   // fp16 + k-permuted
// transposed weights, [N,K] K-major, fp16 + k-permuted
__device__ __align__(256) __half g_WtIn [(size_t)(2 * D_INNER) * D_MODEL];
__device__ __align__(256) __half g_WtDt [(size_t)D_INNER * DT_RANK];
__device__ __align__(256) __half g_WtOut[(size_t)D_MODEL * D_INNER];
// scan chunk transitions
__device__ __align__(256) float g_P [(size_t)NCH * NDN];
__device__ __align__(256) float g_S [(size_t)NCH * NDN];
__device__ __align__(256) float g_h0[(size_t)NCH * NDN];

// ---------------- helpers ----------------
__device__ __forceinline__ uint32_t smem_u32(const void* p) {
    uint32_t a;
    asm("{ .reg .u64 t; cvta.to.shared.u64 t, %1; cvt.u32.u64 %0, t; }"
        : "=r"(a) : "l"(p));
    return a;
}
__device__ __forceinline__ void cp16(uint32_t dst, const void* src) {
    asm volatile("cp.async.cg.shared.global [%0], [%1], 16;"
                 :: "r"(dst), "l"(src) : "memory");
}
#define CP_COMMIT() asm volatile("cp.async.commit_group;" ::: "memory")
#define CP_WAIT3()  asm volatile("cp.async.wait_group 3;"  ::: "memory")

__device__ __forceinline__ void mma16n8k16(float c[4], uint32_t a0, uint32_t a1,
                                           uint32_t a2, uint32_t a3,
                                           uint32_t b0, uint32_t b1) {
    asm volatile(
        "mma.sync.aligned.m16n8k16.row.col.f32.f16.f16.f32 "
        "{%0,%1,%2,%3}, {%4,%5,%6,%7}, {%8,%9}, {%0,%1,%2,%3};"
        : "+f"(c[0]), "+f"(c[1]), "+f"(c[2]), "+f"(c[3])
        : "r"(a0), "r"(a1), "r"(a2), "r"(a3), "r"(b0), "r"(b1));
}

// ---------------- fp16 mma.sync GEMM, BK=32, cp.async pipeline, 2 CTAs/SM ----------
// C[M,N] = A[M,K] @ Bt[N,K]^T + bias.  A/Bt fp16, k-permuted per kperm32.
// SMEM per stage: [128 rows][32 halves] per operand (8KB each, 16KB/stage).
// Thread (r,cq) fragment halves for a whole 32-k chunk = ONE uint4 per row/col.
// 256 threads = 8 warps (2m x 4n), warp tile 64x32.
template <int SOFTPLUS>
__global__ __launch_bounds__(256, 2) void mma_gemm(
    const __half* __restrict__ A,  int lda,
    const __half* __restrict__ Bt, int ldb,
    const float* __restrict__ bias,
    float* __restrict__ C, int ldc, int K)
{
    extern __shared__ __half sm[];     // As[NSTG][128*32] | Bs[NSTG][128*32]
    __half* As = sm;
    __half* Bs = sm + NSTG * 4096;
    const uint32_t sA = smem_u32(As);
    const uint32_t sB = smem_u32(Bs);

    const int tid  = threadIdx.x;
    const int lane = tid & 31;
    const int wid  = tid >> 5;
    const int wm   = wid >> 2;        // 0..1
    const int wn   = wid & 3;         // 0..3
    const int r    = lane >> 2;       // 0..7
    const int cq   = lane & 3;        // 0..3

    const int m0 = blockIdx.y * 128;
    const int n0 = blockIdx.x * 128;
    const __half* Ag = A  + (size_t)m0 * lda;
    const __half* Bg = Bt + (size_t)n0 * ldb;

    const int srow = tid & 127;
    const int sq0  = (tid >> 7) * 2;          // quads {sq0, sq0+1} of 4

    float acc[4][4][4];
#pragma unroll
    for (int i = 0; i < 4; i++)
#pragma unroll
        for (int j = 0; j < 4; j++)
#pragma unroll
            for (int q = 0; q < 4; q++) acc[i][j][q] = 0.f;

    const int NC = K >> 5;     // 32-k chunks

    auto issue = [&](int chunk) {
        const int stage = chunk % NSTG;
        const int k0 = chunk << 5;
#pragma unroll
        for (int t = 0; t < 2; t++) {
            const int q = sq0 + t;            // 16B quad within 64B row
            const uint32_t woff = (uint32_t)((stage * 4096 + srow * 32 + q * 8) << 1);
            cp16(sA + woff, Ag + (size_t)srow * lda + k0 + q * 8);
            cp16(sB + woff, Bg + (size_t)srow * ldb + k0 + q * 8);
        }
    };

#pragma unroll
    for (int s = 0; s < NSTG - 1; s++) {
        if (s < NC) issue(s);
        CP_COMMIT();
    }

    for (int c = 0; c < NC; c++) {
        CP_WAIT3();
        __syncthreads();

        const uint4* A4 = (const uint4*)(As + (c % NSTG) * 4096);
        const uint4* B4 = (const uint4*)(Bs + (c % NSTG) * 4096);

        uint4 bf[4];
#pragma unroll
        for (int ni = 0; ni < 4; ni++)
            bf[ni] = B4[(wn * 32 + ni * 8 + r) * 4 + cq];

#pragma unroll
        for (int mi = 0; mi < 4; mi++) {
            const int rb = wm * 64 + mi * 16 + r;
            const uint4 a0v = A4[rb * 4 + cq];        // row rb  : both k-steps
            const uint4 a1v = A4[(rb + 8) * 4 + cq];  // row rb+8
#pragma unroll
            for (int ni = 0; ni < 4; ni++) {
                // k-step 0 (k 0..15 of chunk)
                mma16n8k16(acc[mi][ni], a0v.x, a1v.x, a0v.y, a1v.y, bf[ni].x, bf[ni].y);
                // k-step 1 (k 16..31)
                mma16n8k16(acc[mi][ni], a0v.z, a1v.z, a0v.w, a1v.w, bf[ni].z, bf[ni].w);
            }
        }

        if (c + NSTG - 1 < NC) issue(c + NSTG - 1);
        CP_COMMIT();
    }

    // ---- epilogue (fp32 out) ----
#pragma unroll
    for (int ni = 0; ni < 4; ni++) {
        const int col = n0 + wn * 32 + ni * 8 + cq * 2;
        const float bv0 = bias[col], bv1 = bias[col + 1];
#pragma unroll
        for (int mi = 0; mi < 4; mi++) {
            const int row0 = m0 + wm * 64 + mi * 16 + r;
            float2 o0, o1;
            o0.x = acc[mi][ni][0] + bv0;  o0.y = acc[mi][ni][1] + bv1;
            o1.x = acc[mi][ni][2] + bv0;  o1.y = acc[mi][ni][3] + bv1;
            if (SOFTPLUS) {
                o0.x = fmaxf(o0.x, 0.f) + log1pf(expf(-fabsf(o0.x)));
                o0.y = fmaxf(o0.y, 0.f) + log1pf(expf(-fabsf(o0.y)));
                o1.x = fmaxf(o1.x, 0.f) + log1pf(expf(-fabsf(o1.x)));
                o1.y = fmaxf(o1.y, 0.f) + log1pf(expf(-fabsf(o1.y)));
            }
            *(float2*)(C + (size_t)row0 * ldc + col)       = o0;
            *(float2*)(C + (size_t)(row0 + 8) * ldc + col) = o1;
        }
    }
}

// -------- weight transpose -> fp16 + k-permute: D[C][perm(R)] --------
__global__ __launch_bounds__(256) void transpose_half_kernel(
    const float* __restrict__ S, __half* __restrict__ D, int R, int C)
{
    __shared__ float t[32][33];
    const int c0 = blockIdx.x * 32, r0 = blockIdx.y * 32;   // r0 mult of 32
    const int x = threadIdx.x, y = threadIdx.y;   // 32 x 8
#pragma unroll
    for (int i = 0; i < 32; i += 8)
        t[y + i][x] = S[(size_t)(r0 + y + i) * C + c0 + x];
    __syncthreads();
    const int xx = kperm32(x);
#pragma unroll
    for (int i = 0; i < 32; i += 8)
        D[(size_t)(c0 + y + i) * R + r0 + xx] = __float2half_rn(t[x][y + i]);
}

// -------- x -> fp16 + k-permute (each thread emits one uint4 = 8 halves) --------
__global__ void half_perm_kernel(const float* __restrict__ S,
                                 __half* __restrict__ D, int n8, int ldq)
{
    const int i = blockIdx.x * blockDim.x + threadIdx.x;
    if (i >= n8) return;
    const int f = i % ldq;               // 8-half quad within row
    const int rowbase = (i - f) * 8;     // row start in floats
    const int g = f >> 2, cq = f & 3;    // 32-group, quad
    const float* src = S + rowbase + g * 32 + cq * 2;
    // j order: 2cq,2cq+1, 2cq+8,2cq+9, 16+2cq,16+2cq+1, 16+2cq+8,16+2cq+9
    __half2 h0 = __floats2half2_rn(src[0],  src[1]);
    __half2 h1 = __floats2half2_rn(src[8],  src[9]);
    __half2 h2 = __floats2half2_rn(src[16], src[17]);
    __half2 h3 = __floats2half2_rn(src[24], src[25]);
    uint4 o;
    o.x = *(uint32_t*)&h0; o.y = *(uint32_t*)&h1;
    o.z = *(uint32_t*)&h2; o.w = *(uint32_t*)&h3;
    ((uint4*)D)[i] = o;
}

// ---------------- skinny GEMM: x_dbl = x_conv @ W_x + b_x ----------------
// 768 threads. cols<64 -> g_dtlr (fp16, k-permuted); cols 64..95 -> g_BC (fp32).
__global__ __launch_bounds__(768) void gemm_n96(
    const float* __restrict__ A,
    const float* __restrict__ B,
    const float* __restrict__ bias,
    int M, int K)
{
    __shared__ float As[32][33];
    __shared__ float Bs[32][96];
    const int tid = threadIdx.x;
    const int m0 = blockIdx.x * 32;
    const int r  = tid / 24;
    const int c0 = (tid % 24) * 4;

    float acc[4] = {0.f, 0.f, 0.f, 0.f};

    for (int k0 = 0; k0 < K; k0 += 32) {
        __syncthreads();
        if (tid < 256) {
            int arow = tid >> 3, akk = (tid & 7) * 4;
            float4 v = *(const float4*)&A[(size_t)(m0 + arow) * K + k0 + akk];
            As[arow][akk + 0] = v.x; As[arow][akk + 1] = v.y;
            As[arow][akk + 2] = v.z; As[arow][akk + 3] = v.w;
        }
        {
            int brw = tid / 24, bcc = (tid % 24) * 4;
            float4 v = *(const float4*)&B[(size_t)(k0 + brw) * XDBL_N + bcc];
            *(float4*)&Bs[brw][bcc] = v;
        }
        __syncthreads();
#pragma unroll
        for (int kk = 0; kk < 32; kk++) {
            const float a = As[r][kk];
            const float4 b4 = *(const float4*)&Bs[kk][c0];
            acc[0] = fmaf(a, b4.x, acc[0]);
            acc[1] = fmaf(a, b4.y, acc[1]);
            acc[2] = fmaf(a, b4.z, acc[2]);
            acc[3] = fmaf(a, b4.w, acc[3]);
        }
    }
    if (c0 < DT_RANK) {
#pragma unroll
        for (int i = 0; i < 4; i++) {
            const int c = c0 + i;
            const int pos = (c & ~31) + kperm32(c & 31);
            g_dtlr[(size_t)(m0 + r) * DT_RANK + pos] =
                __float2half_rn(acc[i] + bias[c]);
        }
    } else {
#pragma unroll
        for (int i = 0; i < 4; i++)
            g_BC[(size_t)(m0 + r) * 32 + (c0 - DT_RANK) + i] = acc[i] + bias[c0 + i];
    }
}

// ---------------- depthwise causal mean-3 conv + SiLU ----------------
__global__ void conv_silu_kernel()
{
    const int i = blockIdx.x * blockDim.x + threadIdx.x;
    if (i >= NROW * D_INNER) return;
    const int d   = i & (D_INNER - 1);
    const int row = i >> 11;
    const int t   = row & (LENGTH - 1);
    const float* p = g_xz + (size_t)row * (2 * D_INNER) + d;
    float v = p[0];
    if (t >= 1) v += p[-(2 * D_INNER)];
    if (t >= 2) v += p[-2 * (2 * D_INNER)];
    v *= (1.0f / 3.0f);
    g_xconv[i] = v / (1.f + __expf(-v));
}

// ======================= 3-phase chunked selective scan =======================
__global__ __launch_bounds__(256) void scan_p1(const float* __restrict__ A_log)
{
    const int TT = 32;
    __shared__ float s_dt[TT][16], s_x[TT][16], s_B[TT][16];

    const int tid   = threadIdx.x;
    const int chunk = blockIdx.x & (NCH - 1);
    const int dblk  = (blockIdx.x >> 4) & 127;
    const int b     = blockIdx.x >> 11;
    const int d0    = dblk << 4;
    const int lane  = tid & 31, w = tid >> 5;
    const int half  = lane >> 4, n = lane & 15;
    const int ch    = (w << 1) | half;
    const int d     = d0 + ch;

    const float a = -__expf(A_log[d * D_STATE + n]);
    float h = 0.f, P = 1.f;
    const size_t rowbase = (size_t)b * LENGTH + (size_t)chunk * CL;

    for (int t0 = 0; t0 < CL; t0 += TT) {
        __syncthreads();
        for (int e = tid; e < TT * 16; e += 256) {
            const int tt = e >> 4, cc = e & 15;
            const size_t row = rowbase + t0 + tt;
            s_dt[tt][cc] = g_dt   [row * D_INNER + d0 + cc];
            s_x [tt][cc] = g_xconv[row * D_INNER + d0 + cc];
            s_B [tt][cc] = g_BC   [row * 32 + cc];
        }
        __syncthreads();
#pragma unroll 8
        for (int tt = 0; tt < TT; tt++) {
            const float dtv = s_dt[tt][ch];
            const float dA  = __expf(a * dtv);
            P *= dA;
            h = fmaf(dA, h, dtv * s_x[tt][ch] * s_B[tt][n]);
        }
    }
    const size_t idx = ((size_t)b * D_INNER + d) * D_STATE + n;
    g_P[(size_t)chunk * NDN + idx] = P;
    g_S[(size_t)chunk * NDN + idx] = h;
}

__global__ __launch_bounds__(256) void scan_p2()
{
    const int i = blockIdx.x * blockDim.x + threadIdx.x;
    if (i >= NDN) return;
    float h = 0.f;
#pragma unroll
    for (int c = 0; c < NCH; c++) {
        g_h0[(size_t)c * NDN + i] = h;
        h = fmaf(g_P[(size_t)c * NDN + i], h, g_S[(size_t)c * NDN + i]);
    }
}

__global__ __launch_bounds__(256) void scan_p3(const float* __restrict__ A_log,
                                               const float* __restrict__ Dv)
{
    const int TT = 32;
    __shared__ float s_dt[TT][16], s_x[TT][16], s_B[TT][16], s_C[TT][16];

    const int tid   = threadIdx.x;
    const int chunk = blockIdx.x & (NCH - 1);
    const int dblk  = (blockIdx.x >> 4) & 127;
    const int b     = blockIdx.x >> 11;
    const int d0    = dblk << 4;
    const int lane  = tid & 31, w = tid >> 5;
    const int half  = lane >> 4, n = lane & 15;
    const int ch    = (w << 1) | half;
    const int d     = d0 + ch;

    const float a  = -__expf(A_log[d * D_STATE + n]);
    const float Dd = Dv[d];
    const size_t idx = ((size_t)b * D_INNER + d) * D_STATE + n;
    float h = g_h0[(size_t)chunk * NDN + idx];
    const size_t rowbase = (size_t)b * LENGTH + (size_t)chunk * CL;

    const int dperm = (d & ~31) + kperm32(d & 31);   // fp16 k-permuted gate slot

    for (int t0 = 0; t0 < CL; t0 += TT) {
        __syncthreads();
        for (int e = tid; e < TT * 16; e += 256) {
            const int tt = e >> 4, cc = e & 15;
            const size_t row = rowbase + t0 + tt;
            s_dt[tt][cc] = g_dt   [row * D_INNER + d0 + cc];
            s_x [tt][cc] = g_xconv[row * D_INNER + d0 + cc];
            s_B [tt][cc] = g_BC   [row * 32 + cc];
            s_C [tt][cc] = g_BC   [row * 32 + 16 + cc];
        }
        __syncthreads();
#pragma unroll 4
        for (int tt = 0; tt < TT; tt++) {
            const float dtv = s_dt[tt][ch];
            const float xv  = s_x [tt][ch];
            const float dA  = __expf(a * dtv);
            h = fmaf(dA, h, dtv * xv * s_B[tt][n]);
            float yc = h * s_C[tt][n];
            yc += __shfl_xor_sync(0xffffffffu, yc, 8);
            yc += __shfl_xor_sync(0xffffffffu, yc, 4);
            yc += __shfl_xor_sync(0xffffffffu, yc, 2);
            yc += __shfl_xor_sync(0xffffffffu, yc, 1);
            if (n == 0) {
                const size_t row = rowbase + t0 + tt;
                const float zv = g_xz[row * (2 * D_INNER) + D_INNER + d];
                const float sz = zv / (1.f + __expf(-zv));
                const float y  = fmaf(xv, Dd, yc);
                g_gate[row * D_INNER + dperm] = __float2half_rn(y * sz);
            }
        }
    }
}

// ---------------- host launcher ----------------
extern "C" void kernel_launch(void* const* d_in, const int* in_sizes, int n_in,
                              void* d_out, int out_size)
{
    (void)in_sizes; (void)n_in; (void)out_size;
    const float* x     = (const float*)d_in[0];
    const float* W_in  = (const float*)d_in[1];
    const float* b_in  = (const float*)d_in[2];
    const float* W_x   = (const float*)d_in[3];
    const float* b_x   = (const float*)d_in[4];
    const float* W_dt  = (const float*)d_in[5];
    const float* b_dt  = (const float*)d_in[6];
    const float* A_log = (const float*)d_in[7];
    const float* Dp    = (const float*)d_in[8];
    const float* W_out = (const float*)d_in[9];
    const float* b_out = (const float*)d_in[10];
    float* out = (float*)d_out;

    float *xz, *xconv, *dt;
    __half *gate, *xr, *WtIn, *WtDt, *WtOut, *dtlr;
    cudaGetSymbolAddress((void**)&xz,    g_xz);
    cudaGetSymbolAddress((void**)&xconv, g_xconv);
    cudaGetSymbolAddress((void**)&dt,    g_dt);
    cudaGetSymbolAddress((void**)&gate,  g_gate);
    cudaGetSymbolAddress((void**)&xr,    g_xr);
    cudaGetSymbolAddress((void**)&WtIn,  g_WtIn);
    cudaGetSymbolAddress((void**)&WtDt,  g_WtDt);
    cudaGetSymbolAddress((void**)&WtOut, g_WtOut);
    cudaGetSymbolAddress((void**)&dtlr,  g_dtlr);

    const int DSMEM = NSTG * 4096 * 2 * 2;   // 80KB -> 2 CTAs/SM
    cudaFuncSetAttribute(mma_gemm<0>, cudaFuncAttributeMaxDynamicSharedMemorySize, DSMEM);
    cudaFuncSetAttribute(mma_gemm<1>, cudaFuncAttributeMaxDynamicSharedMemorySize, DSMEM);

    // 0-2) x -> fp16+perm, W_in / W_dt -> transposed fp16+perm
    half_perm_kernel<<<(NROW * D_MODEL / 8 + 255) / 256, 256>>>(
        x, xr, NROW * D_MODEL / 8, D_MODEL / 8);
    transpose_half_kernel<<<dim3(4096 / 32, 1024 / 32), dim3(32, 8)>>>(W_in, WtIn, 1024, 4096);
    transpose_half_kernel<<<dim3(2048 / 32,   64 / 32), dim3(32, 8)>>>(W_dt, WtDt,   64, 2048);

    // 3) xz = x @ W_in + b_in      [4096,1024] x [1024,4096]   <- profiled slot
    mma_gemm<0><<<dim3(4096 / 128, NROW / 128), 256, DSMEM>>>(
        xr, D_MODEL, WtIn, D_MODEL, b_in, xz, 2 * D_INNER, D_MODEL);

    // 4) causal mean-3 conv + SiLU
    conv_silu_kernel<<<(NROW * D_INNER) / 256, 256>>>();

    // 5) x_dbl = x_conv @ W_x + b_x -> dtlr (fp16) | BC (fp32)
    gemm_n96<<<NROW / 32, 768>>>(xconv, W_x, b_x, NROW, D_INNER);

    // 6) dt = softplus(dtlr @ W_dt + b_dt)   [4096,64] x [64,2048]
    mma_gemm<1><<<dim3(D_INNER / 128, NROW / 128), 256, DSMEM>>>(
        dtlr, DT_RANK, WtDt, DT_RANK, b_dt, dt, D_INNER, DT_RANK);

    // 7-9) chunked selective scan
    scan_p1<<<BATCH * 128 * NCH, 256>>>(A_log);
    scan_p2<<<NDN / 256, 256>>>();
    scan_p3<<<BATCH * 128 * NCH, 256>>>(A_log, Dp);

    // 10) W_out -> transposed fp16+perm
    transpose_half_kernel<<<dim3(1024 / 32, 2048 / 32), dim3(32, 8)>>>(W_out, WtOut, 2048, 1024);

    // 11) out = gate @ W_out + b_out   [4096,2048] x [2048,1024]
    mma_gemm<0><<<dim3(D_MODEL / 128, NROW / 128), 256, DSMEM>>>(
        gate, D_INNER, WtOut, D_INNER, b_out, out, D_MODEL, D_INNER);
}

// round 10
// speedup vs baseline: 1.3856x; 1.0645x over previous
#include <cuda_runtime.h>
#include <cuda_fp16.h>
#include <math.h>
#include <stdint.h>

// ---------------- problem constants ----------------
#define D_MODEL  1024
#define D_STATE  16
#define D_INNER  2048
#define DT_RANK  64
#define BATCH    2
#define LENGTH   2048
#define NROW     (BATCH * LENGTH)       // 4096
#define XDBL_N   96
#define NCH      32                     // scan time-chunks
#define CL       (LENGTH / NCH)         // 64 steps per chunk
#define NDN      (BATCH * D_INNER * D_STATE)   // 65536
#define NSTG     5                      // GEMM pipeline stages (BK=32)
#define N96S     4                      // n96 split-K factor

// k-permutation within 32-element groups (fp16 m16n8k16 fragment gather):
__host__ __device__ __forceinline__ int kperm32(int k) {
    return (((k >> 1) & 3) << 3) + (k & 1) + (((k >> 3) & 1) << 1) + (((k >> 4) & 1) << 2);
}

// ---------------- scratch (device globals; no allocation allowed) ----------------
__device__ __align__(256) float  g_xz   [(size_t)NROW * (2 * D_INNER)];
__device__ __align__(256) float  g_xconv[(size_t)NROW * D_INNER];
__device__ __align__(256) __half g_dtlr [(size_t)NROW * DT_RANK];   // k-permuted fp16
__device__ __align__(256) float  g_BC   [(size_t)NROW * 32];        // B|C for scan
__device__ __align__(256) float  g_dt   [(size_t)NROW * D_INNER];
__device__ __align__(256) __half g_gate [(size_t)NROW * D_INNER];   // fp16 + k-permuted
__device__ __align__(256) __half g_xr   [(size_t)NROW * D_MODEL];   // fp16 + k-permuted
// transposed weights, [N,K] K-major, fp16 + k-permuted
__device__ __align__(256) __half g_WtIn [(size_t)(2 * D_INNER) * D_MODEL];
__device__ __align__(256) __half g_WtDt [(size_t)D_INNER * DT_RANK];
__device__ __align__(256) __half g_WtOut[(size_t)D_MODEL * D_INNER];
// scan chunk transitions
__device__ __align__(256) float g_P [(size_t)NCH * NDN];
__device__ __align__(256) float g_S [(size_t)NCH * NDN];
__device__ __align__(256) float g_h0[(size_t)NCH * NDN];
// n96 split-K partials: [N96S][NROW][96]
__device__ __align__(256) float g_n96p[(size_t)N96S * NROW * XDBL_N];

// ---------------- helpers ----------------
__device__ __forceinline__ uint32_t smem_u32(const void* p) {
    uint32_t a;
    asm("{ .reg .u64 t; cvta.to.shared.u64 t, %1; cvt.u32.u64 %0, t; }"
        : "=r"(a) : "l"(p));
    return a;
}
__device__ __forceinline__ void cp16(uint32_t dst, const void* src) {
    asm volatile("cp.async.cg.shared.global [%0], [%1], 16;"
                 :: "r"(dst), "l"(src) : "memory");
}
#define CP_COMMIT() asm volatile("cp.async.commit_group;" ::: "memory")
#define CP_WAIT3()  asm volatile("cp.async.wait_group 3;"  ::: "memory")

__device__ __forceinline__ void mma16n8k16(float c[4], uint32_t a0, uint32_t a1,
                                           uint32_t a2, uint32_t a3,
                                           uint32_t b0, uint32_t b1) {
    asm volatile(
        "mma.sync.aligned.m16n8k16.row.col.f32.f16.f16.f32 "
        "{%0,%1,%2,%3}, {%4,%5,%6,%7}, {%8,%9}, {%0,%1,%2,%3};"
        : "+f"(c[0]), "+f"(c[1]), "+f"(c[2]), "+f"(c[3])
        : "r"(a0), "r"(a1), "r"(a2), "r"(a3), "r"(b0), "r"(b1));
}

// ---------------- fp16 mma.sync GEMM, BK=32, cp.async pipeline, 2 CTAs/SM ----------
template <int SOFTPLUS>
__global__ __launch_bounds__(256, 2) void mma_gemm(
    const __half* __restrict__ A,  int lda,
    const __half* __restrict__ Bt, int ldb,
    const float* __restrict__ bias,
    float* __restrict__ C, int ldc, int K)
{
    extern __shared__ __half sm[];     // As[NSTG][128*32] | Bs[NSTG][128*32]
    __half* As = sm;
    __half* Bs = sm + NSTG * 4096;
    const uint32_t sA = smem_u32(As);
    const uint32_t sB = smem_u32(Bs);

    const int tid  = threadIdx.x;
    const int lane = tid & 31;
    const int wid  = tid >> 5;
    const int wm   = wid >> 2;
    const int wn   = wid & 3;
    const int r    = lane >> 2;
    const int cq   = lane & 3;

    const int m0 = blockIdx.y * 128;
    const int n0 = blockIdx.x * 128;
    const __half* Ag = A  + (size_t)m0 * lda;
    const __half* Bg = Bt + (size_t)n0 * ldb;

    const int srow = tid & 127;
    const int sq0  = (tid >> 7) * 2;

    float acc[4][4][4];
#pragma unroll
    for (int i = 0; i < 4; i++)
#pragma unroll
        for (int j = 0; j < 4; j++)
#pragma unroll
            for (int q = 0; q < 4; q++) acc[i][j][q] = 0.f;

    const int NC = K >> 5;

    auto issue = [&](int chunk) {
        const int stage = chunk % NSTG;
        const int k0 = chunk << 5;
#pragma unroll
        for (int t = 0; t < 2; t++) {
            const int q = sq0 + t;
            const uint32_t woff = (uint32_t)((stage * 4096 + srow * 32 + q * 8) << 1);
            cp16(sA + woff, Ag + (size_t)srow * lda + k0 + q * 8);
            cp16(sB + woff, Bg + (size_t)srow * ldb + k0 + q * 8);
        }
    };

#pragma unroll
    for (int s = 0; s < NSTG - 1; s++) {
        if (s < NC) issue(s);
        CP_COMMIT();
    }

    for (int c = 0; c < NC; c++) {
        CP_WAIT3();
        __syncthreads();

        const uint4* A4 = (const uint4*)(As + (c % NSTG) * 4096);
        const uint4* B4 = (const uint4*)(Bs + (c % NSTG) * 4096);

        uint4 bf[4];
#pragma unroll
        for (int ni = 0; ni < 4; ni++)
            bf[ni] = B4[(wn * 32 + ni * 8 + r) * 4 + cq];

#pragma unroll
        for (int mi = 0; mi < 4; mi++) {
            const int rb = wm * 64 + mi * 16 + r;
            const uint4 a0v = A4[rb * 4 + cq];
            const uint4 a1v = A4[(rb + 8) * 4 + cq];
#pragma unroll
            for (int ni = 0; ni < 4; ni++) {
                mma16n8k16(acc[mi][ni], a0v.x, a1v.x, a0v.y, a1v.y, bf[ni].x, bf[ni].y);
                mma16n8k16(acc[mi][ni], a0v.z, a1v.z, a0v.w, a1v.w, bf[ni].z, bf[ni].w);
            }
        }

        if (c + NSTG - 1 < NC) issue(c + NSTG - 1);
        CP_COMMIT();
    }

#pragma unroll
    for (int ni = 0; ni < 4; ni++) {
        const int col = n0 + wn * 32 + ni * 8 + cq * 2;
        const float bv0 = bias[col], bv1 = bias[col + 1];
#pragma unroll
        for (int mi = 0; mi < 4; mi++) {
            const int row0 = m0 + wm * 64 + mi * 16 + r;
            float2 o0, o1;
            o0.x = acc[mi][ni][0] + bv0;  o0.y = acc[mi][ni][1] + bv1;
            o1.x = acc[mi][ni][2] + bv0;  o1.y = acc[mi][ni][3] + bv1;
            if (SOFTPLUS) {
                o0.x = fmaxf(o0.x, 0.f) + log1pf(expf(-fabsf(o0.x)));
                o0.y = fmaxf(o0.y, 0.f) + log1pf(expf(-fabsf(o0.y)));
                o1.x = fmaxf(o1.x, 0.f) + log1pf(expf(-fabsf(o1.x)));
                o1.y = fmaxf(o1.y, 0.f) + log1pf(expf(-fabsf(o1.y)));
            }
            *(float2*)(C + (size_t)row0 * ldc + col)       = o0;
            *(float2*)(C + (size_t)(row0 + 8) * ldc + col) = o1;
        }
    }
}

// -------- weight transpose -> fp16 + k-permute --------
__global__ __launch_bounds__(256) void transpose_half_kernel(
    const float* __restrict__ S, __half* __restrict__ D, int R, int C)
{
    __shared__ float t[32][33];
    const int c0 = blockIdx.x * 32, r0 = blockIdx.y * 32;
    const int x = threadIdx.x, y = threadIdx.y;
#pragma unroll
    for (int i = 0; i < 32; i += 8)
        t[y + i][x] = S[(size_t)(r0 + y + i) * C + c0 + x];
    __syncthreads();
    const int xx = kperm32(x);
#pragma unroll
    for (int i = 0; i < 32; i += 8)
        D[(size_t)(c0 + y + i) * R + r0 + xx] = __float2half_rn(t[x][y + i]);
}

// -------- x -> fp16 + k-permute --------
__global__ void half_perm_kernel(const float* __restrict__ S,
                                 __half* __restrict__ D, int n8, int ldq)
{
    const int i = blockIdx.x * blockDim.x + threadIdx.x;
    if (i >= n8) return;
    const int f = i % ldq;
    const int rowbase = (i - f) * 8;
    const int g = f >> 2, cq = f & 3;
    const float* src = S + rowbase + g * 32 + cq * 2;
    __half2 h0 = __floats2half2_rn(src[0],  src[1]);
    __half2 h1 = __floats2half2_rn(src[8],  src[9]);
    __half2 h2 = __floats2half2_rn(src[16], src[17]);
    __half2 h3 = __floats2half2_rn(src[24], src[25]);
    uint4 o;
    o.x = *(uint32_t*)&h0; o.y = *(uint32_t*)&h1;
    o.z = *(uint32_t*)&h2; o.w = *(uint32_t*)&h3;
    ((uint4*)D)[i] = o;
}

// ---------------- skinny GEMM, split-K: partial[s] = A[:,Ks] @ B[Ks,:] ----------
// grid (M/32, N96S), 768 threads; each block does K/N96S of the reduction.
__global__ __launch_bounds__(768) void gemm_n96_split(
    const float* __restrict__ A,
    const float* __restrict__ B,
    int M, int K)
{
    __shared__ float As[32][33];
    __shared__ float Bs[32][96];
    const int tid = threadIdx.x;
    const int m0 = blockIdx.x * 32;
    const int s  = blockIdx.y;
    const int r  = tid / 24;
    const int c0 = (tid % 24) * 4;
    const int kbeg = s * (K / N96S), kend = kbeg + K / N96S;

    float acc[4] = {0.f, 0.f, 0.f, 0.f};

    for (int k0 = kbeg; k0 < kend; k0 += 32) {
        __syncthreads();
        if (tid < 256) {
            int arow = tid >> 3, akk = (tid & 7) * 4;
            float4 v = *(const float4*)&A[(size_t)(m0 + arow) * K + k0 + akk];
            As[arow][akk + 0] = v.x; As[arow][akk + 1] = v.y;
            As[arow][akk + 2] = v.z; As[arow][akk + 3] = v.w;
        }
        {
            int brw = tid / 24, bcc = (tid % 24) * 4;
            float4 v = *(const float4*)&B[(size_t)(k0 + brw) * XDBL_N + bcc];
            *(float4*)&Bs[brw][bcc] = v;
        }
        __syncthreads();
#pragma unroll
        for (int kk = 0; kk < 32; kk++) {
            const float a = As[r][kk];
            const float4 b4 = *(const float4*)&Bs[kk][c0];
            acc[0] = fmaf(a, b4.x, acc[0]);
            acc[1] = fmaf(a, b4.y, acc[1]);
            acc[2] = fmaf(a, b4.z, acc[2]);
            acc[3] = fmaf(a, b4.w, acc[3]);
        }
    }
    float* P = g_n96p + (size_t)s * NROW * XDBL_N;
#pragma unroll
    for (int i = 0; i < 4; i++)
        P[(size_t)(m0 + r) * XDBL_N + c0 + i] = acc[i];
}

// ---- combine n96 partials: + bias; cols<64 -> dtlr (fp16+perm), else -> BC ----
__global__ void n96_combine(const float* __restrict__ bias, int n)
{
    const int i = blockIdx.x * blockDim.x + threadIdx.x;
    if (i >= n) return;
    const int row = i / XDBL_N, c = i % XDBL_N;
    float v = bias[c];
#pragma unroll
    for (int s = 0; s < N96S; s++)
        v += g_n96p[(size_t)s * NROW * XDBL_N + i];
    if (c < DT_RANK) {
        const int pos = (c & ~31) + kperm32(c & 31);
        g_dtlr[(size_t)row * DT_RANK + pos] = __float2half_rn(v);
    } else {
        g_BC[(size_t)row * 32 + (c - DT_RANK)] = v;
    }
}

// ---------------- depthwise causal mean-3 conv + SiLU (float4) ----------------
__global__ void conv_silu_kernel()
{
    const int i = blockIdx.x * blockDim.x + threadIdx.x;   // group of 4 d's
    if (i >= NROW * D_INNER / 4) return;
    const int d4  = (i * 4) & (D_INNER - 1);
    const int row = (i * 4) >> 11;
    const int t   = row & (LENGTH - 1);
    const float* p = g_xz + (size_t)row * (2 * D_INNER) + d4;
    float4 v = *(const float4*)p;
    if (t >= 1) {
        float4 w = *(const float4*)(p - 2 * D_INNER);
        v.x += w.x; v.y += w.y; v.z += w.z; v.w += w.w;
    }
    if (t >= 2) {
        float4 w = *(const float4*)(p - 4 * D_INNER);
        v.x += w.x; v.y += w.y; v.z += w.z; v.w += w.w;
    }
    v.x *= (1.0f / 3.0f); v.y *= (1.0f / 3.0f);
    v.z *= (1.0f / 3.0f); v.w *= (1.0f / 3.0f);
    v.x /= (1.f + __expf(-v.x)); v.y /= (1.f + __expf(-v.y));
    v.z /= (1.f + __expf(-v.z)); v.w /= (1.f + __expf(-v.w));
    *(float4*)(g_xconv + (size_t)row * D_INNER + d4) = v;
}

// ======================= 3-phase chunked selective scan (NCH=32) ====================
// blockIdx.x = ((b*128 + dblk)*NCH + chunk); 256 threads.
__global__ __launch_bounds__(256) void scan_p1(const float* __restrict__ A_log)
{
    const int TT = 32;
    __shared__ float s_dt[TT][16], s_x[TT][16], s_B[TT][16];

    const int tid   = threadIdx.x;
    const int chunk = blockIdx.x & (NCH - 1);
    const int dblk  = (blockIdx.x >> 5) & 127;
    const int b     = blockIdx.x >> 12;
    const int d0    = dblk << 4;
    const int lane  = tid & 31, w = tid >> 5;
    const int half  = lane >> 4, n = lane & 15;
    const int ch    = (w << 1) | half;
    const int d     = d0 + ch;

    const float a = -__expf(A_log[d * D_STATE + n]);
    float h = 0.f, P = 1.f;
    const size_t rowbase = (size_t)b * LENGTH + (size_t)chunk * CL;

    for (int t0 = 0; t0 < CL; t0 += TT) {
        __syncthreads();
        for (int e = tid; e < TT * 16; e += 256) {
            const int tt = e >> 4, cc = e & 15;
            const size_t row = rowbase + t0 + tt;
            s_dt[tt][cc] = g_dt   [row * D_INNER + d0 + cc];
            s_x [tt][cc] = g_xconv[row * D_INNER + d0 + cc];
            s_B [tt][cc] = g_BC   [row * 32 + cc];
        }
        __syncthreads();
#pragma unroll 8
        for (int tt = 0; tt < TT; tt++) {
            const float dtv = s_dt[tt][ch];
            const float dA  = __expf(a * dtv);
            P *= dA;
            h = fmaf(dA, h, dtv * s_x[tt][ch] * s_B[tt][n]);
        }
    }
    const size_t idx = ((size_t)b * D_INNER + d) * D_STATE + n;
    g_P[(size_t)chunk * NDN + idx] = P;
    g_S[(size_t)chunk * NDN + idx] = h;
}

__global__ __launch_bounds__(256) void scan_p2()
{
    const int i = blockIdx.x * blockDim.x + threadIdx.x;
    if (i >= NDN) return;
    float h = 0.f;
#pragma unroll
    for (int c = 0; c < NCH; c++) {
        g_h0[(size_t)c * NDN + i] = h;
        h = fmaf(g_P[(size_t)c * NDN + i], h, g_S[(size_t)c * NDN + i]);
    }
}

__global__ __launch_bounds__(256) void scan_p3(const float* __restrict__ A_log,
                                               const float* __restrict__ Dv)
{
    const int TT = 32;
    __shared__ float s_dt[TT][16], s_x[TT][16], s_B[TT][16], s_C[TT][16];

    const int tid   = threadIdx.x;
    const int chunk = blockIdx.x & (NCH - 1);
    const int dblk  = (blockIdx.x >> 5) & 127;
    const int b     = blockIdx.x >> 12;
    const int d0    = dblk << 4;
    const int lane  = tid & 31, w = tid >> 5;
    const int half  = lane >> 4, n = lane & 15;
    const int ch    = (w << 1) | half;
    const int d     = d0 + ch;

    const float a  = -__expf(A_log[d * D_STATE + n]);
    const float Dd = Dv[d];
    const size_t idx = ((size_t)b * D_INNER + d) * D_STATE + n;
    float h = g_h0[(size_t)chunk * NDN + idx];
    const size_t rowbase = (size_t)b * LENGTH + (size_t)chunk * CL;

    const int dperm = (d & ~31) + kperm32(d & 31);

    for (int t0 = 0; t0 < CL; t0 += TT) {
        __syncthreads();
        for (int e = tid; e < TT * 16; e += 256) {
            const int tt = e >> 4, cc = e & 15;
            const size_t row = rowbase + t0 + tt;
            s_dt[tt][cc] = g_dt   [row * D_INNER + d0 + cc];
            s_x [tt][cc] = g_xconv[row * D_INNER + d0 + cc];
            s_B [tt][cc] = g_BC   [row * 32 + cc];
            s_C [tt][cc] = g_BC   [row * 32 + 16 + cc];
        }
        __syncthreads();
#pragma unroll 4
        for (int tt = 0; tt < TT; tt++) {
            const float dtv = s_dt[tt][ch];
            const float xv  = s_x [tt][ch];
            const float dA  = __expf(a * dtv);
            h = fmaf(dA, h, dtv * xv * s_B[tt][n]);
            float yc = h * s_C[tt][n];
            yc += __shfl_xor_sync(0xffffffffu, yc, 8);
            yc += __shfl_xor_sync(0xffffffffu, yc, 4);
            yc += __shfl_xor_sync(0xffffffffu, yc, 2);
            yc += __shfl_xor_sync(0xffffffffu, yc, 1);
            if (n == 0) {
                const size_t row = rowbase + t0 + tt;
                const float zv = g_xz[row * (2 * D_INNER) + D_INNER + d];
                const float sz = zv / (1.f + __expf(-zv));
                const float y  = fmaf(xv, Dd, yc);
                g_gate[row * D_INNER + dperm] = __float2half_rn(y * sz);
            }
        }
    }
}

// ---------------- host launcher ----------------
extern "C" void kernel_launch(void* const* d_in, const int* in_sizes, int n_in,
                              void* d_out, int out_size)
{
    (void)in_sizes; (void)n_in; (void)out_size;
    const float* x     = (const float*)d_in[0];
    const float* W_in  = (const float*)d_in[1];
    const float* b_in  = (const float*)d_in[2];
    const float* W_x   = (const float*)d_in[3];
    const float* b_x   = (const float*)d_in[4];
    const float* W_dt  = (const float*)d_in[5];
    const float* b_dt  = (const float*)d_in[6];
    const float* A_log = (const float*)d_in[7];
    const float* Dp    = (const float*)d_in[8];
    const float* W_out = (const float*)d_in[9];
    const float* b_out = (const float*)d_in[10];
    float* out = (float*)d_out;

    float *xz, *xconv, *dt;
    __half *gate, *xr, *WtIn, *WtDt, *WtOut, *dtlr;
    cudaGetSymbolAddress((void**)&xz,    g_xz);
    cudaGetSymbolAddress((void**)&xconv, g_xconv);
    cudaGetSymbolAddress((void**)&dt,    g_dt);
    cudaGetSymbolAddress((void**)&gate,  g_gate);
    cudaGetSymbolAddress((void**)&xr,    g_xr);
    cudaGetSymbolAddress((void**)&WtIn,  g_WtIn);
    cudaGetSymbolAddress((void**)&WtDt,  g_WtDt);
    cudaGetSymbolAddress((void**)&WtOut, g_WtOut);
    cudaGetSymbolAddress((void**)&dtlr,  g_dtlr);

    const int DSMEM = NSTG * 4096 * 2 * 2;   // 80KB -> 2 CTAs/SM
    cudaFuncSetAttribute(mma_gemm<0>, cudaFuncAttributeMaxDynamicSharedMemorySize, DSMEM);
    cudaFuncSetAttribute(mma_gemm<1>, cudaFuncAttributeMaxDynamicSharedMemorySize, DSMEM);

    // 0-2) x -> fp16+perm, W_in / W_dt -> transposed fp16+perm
    half_perm_kernel<<<(NROW * D_MODEL / 8 + 255) / 256, 256>>>(
        x, xr, NROW * D_MODEL / 8, D_MODEL / 8);
    transpose_half_kernel<<<dim3(4096 / 32, 1024 / 32), dim3(32, 8)>>>(W_in, WtIn, 1024, 4096);
    transpose_half_kernel<<<dim3(2048 / 32,   64 / 32), dim3(32, 8)>>>(W_dt, WtDt,   64, 2048);

    // 3) xz = x @ W_in + b_in      [4096,1024] x [1024,4096]   <- profiled slot
    mma_gemm<0><<<dim3(4096 / 128, NROW / 128), 256, DSMEM>>>(
        xr, D_MODEL, WtIn, D_MODEL, b_in, xz, 2 * D_INNER, D_MODEL);

    // 4) causal mean-3 conv + SiLU (float4)
    conv_silu_kernel<<<(NROW * D_INNER / 4) / 256, 256>>>();

    // 5) x_dbl = x_conv @ W_x + b_x  (split-K=4 partials + combine)
    gemm_n96_split<<<dim3(NROW / 32, N96S), 768>>>(xconv, W_x, NROW, D_INNER);
    n96_combine<<<(NROW * XDBL_N + 255) / 256, 256>>>(b_x, NROW * XDBL_N);

    // 6) dt = softplus(dtlr @ W_dt + b_dt)   [4096,64] x [64,2048]
    mma_gemm<1><<<dim3(D_INNER / 128, NROW / 128), 256, DSMEM>>>(
        dtlr, DT_RANK, WtDt, DT_RANK, b_dt, dt, D_INNER, DT_RANK);

    // 7-9) chunked selective scan (NCH=32)
    scan_p1<<<BATCH * 128 * NCH, 256>>>(A_log);
    scan_p2<<<NDN / 256, 256>>>();
    scan_p3<<<BATCH * 128 * NCH, 256>>>(A_log, Dp);

    // 10) W_out -> transposed fp16+perm
    transpose_half_kernel<<<dim3(1024 / 32, 2048 / 32), dim3(32, 8)>>>(W_out, WtOut, 2048, 1024);

    // 11) out = gate @ W_out + b_out   [4096,2048] x [2048,1024]
    mma_gemm<0><<<dim3(D_MODEL / 128, NROW / 128), 256, DSMEM>>>(
        gate, D_INNER, WtOut, D_INNER, b_out, out, D_MODEL, D_INNER);
}